// round 3
// baseline (speedup 1.0000x reference)
#include <cuda_runtime.h>
#include <cuda_bf16.h>
#include <cstdint>

// ============================================================================
// MLPList: B=32768 rows, 63 stacked MLPs (64->64->64->1), causal input mask.
// Strategy: warp-level mma.sync bf16 (hi/lo split for fp32-grade accuracy),
// weights pre-masked/transposed/split/swizzled into device scratch, cp.async
// double-buffered staging, register-only layer1->layer2 handoff.
// ============================================================================
#define NI 63
#define DK 64
#define HN 64

// Device scratch: per-i weight images (B-operand [n][k] bf16, XOR-swizzled),
// 4 matrices x 8192B = 32768B per i; plus packed bias vectors.
__device__ __align__(16) unsigned char g_wpack[NI * 32768];
__device__ __align__(16) float g_bpack[NI * 208];   // b1[64], b2[64], w3[64], b3, pad
__device__ float g_o0;

// ---------------------------------------------------------------------------
__device__ __forceinline__ uint32_t smem_u32(const void* p) {
    uint32_t a;
    asm("{ .reg .u64 t; cvta.to.shared.u64 t, %1; cvt.u32.u64 %0, t; }"
        : "=r"(a) : "l"(p));
    return a;
}

// hi/lo bf16 split of a float pair, packed into two u32 (low element first)
__device__ __forceinline__ void split2(float a, float b, uint32_t& hi, uint32_t& lo) {
    __nv_bfloat16 ha = __float2bfloat16(a), hb = __float2bfloat16(b);
    float ra = a - __bfloat162float(ha);
    float rb = b - __bfloat162float(hb);
    __nv_bfloat16 la = __float2bfloat16(ra), lb = __float2bfloat16(rb);
    hi = ((uint32_t)__bfloat16_as_ushort(hb) << 16) | (uint32_t)__bfloat16_as_ushort(ha);
    lo = ((uint32_t)__bfloat16_as_ushort(lb) << 16) | (uint32_t)__bfloat16_as_ushort(la);
}

// m16n8k16 row.col bf16 MMA, fp32 accumulate in registers
__device__ __forceinline__ void mma16816(float* d, const uint32_t* a, const uint32_t* b) {
    asm volatile(
        "mma.sync.aligned.m16n8k16.row.col.f32.bf16.bf16.f32 "
        "{%0,%1,%2,%3}, {%4,%5,%6,%7}, {%8,%9}, {%0,%1,%2,%3};"
        : "+f"(d[0]), "+f"(d[1]), "+f"(d[2]), "+f"(d[3])
        : "r"(a[0]), "r"(a[1]), "r"(a[2]), "r"(a[3]), "r"(b[0]), "r"(b[1]));
}

// ============================================================================
// Prep kernels
// ============================================================================
// Weight image: element (n,k) at byte n*128 + ((k*2) ^ ((n&7)<<4)).
__global__ void prep_weights_kernel(const float* __restrict__ W1,
                                    const float* __restrict__ W2) {
    int idx = blockIdx.x * blockDim.x + threadIdx.x;
    if (idx >= NI * DK * HN) return;
    int i = idx >> 12;
    int n = (idx >> 6) & 63;   // hidden index (B-operand row)
    int k = idx & 63;          // contraction index
    uint32_t off = (uint32_t)(n * 128) + (uint32_t)((k * 2) ^ ((n & 7) << 4));
    unsigned char* base = g_wpack + (size_t)i * 32768;

    float v1 = (k <= i) ? W1[((size_t)i * DK + k) * HN + n] : 0.0f;   // masked, transposed
    __nv_bfloat16 h1 = __float2bfloat16(v1);
    __nv_bfloat16 l1 = __float2bfloat16(v1 - __bfloat162float(h1));
    *(__nv_bfloat16*)(base + 0 * 8192 + off) = h1;
    *(__nv_bfloat16*)(base + 1 * 8192 + off) = l1;

    float v2 = W2[((size_t)i * HN + k) * HN + n];
    __nv_bfloat16 h2 = __float2bfloat16(v2);
    __nv_bfloat16 l2 = __float2bfloat16(v2 - __bfloat162float(h2));
    *(__nv_bfloat16*)(base + 2 * 8192 + off) = h2;
    *(__nv_bfloat16*)(base + 3 * 8192 + off) = l2;
}

__global__ void prep_bias_kernel(const float* __restrict__ b1, const float* __restrict__ b2,
                                 const float* __restrict__ W3, const float* __restrict__ b3) {
    int idx = blockIdx.x * blockDim.x + threadIdx.x;
    if (idx >= NI * 208) return;
    int i = idx / 208, t = idx % 208;
    float v = 0.0f;
    if (t < 64)       v = b1[i * 64 + t];
    else if (t < 128) v = b2[i * 64 + (t - 64)];
    else if (t < 192) v = W3[i * 64 + (t - 128)];
    else if (t == 192) v = b3[i];
    g_bpack[i * 208 + t] = v;
}

// Dim-0 MLP (batch-constant), one 64-thread block
__global__ void prep_dim0_kernel(const float* __restrict__ w01, const float* __restrict__ b01,
                                 const float* __restrict__ w02, const float* __restrict__ b02,
                                 const float* __restrict__ w03, const float* __restrict__ b03) {
    __shared__ float h0s[64];
    __shared__ float ps[64];
    int h = threadIdx.x;
    float a = b01[h];
#pragma unroll
    for (int t = 0; t < 10; t++) {
        float v = 0.1f * (-5.0f + (float)t * (10.0f / 9.0f));
        a = fmaf(v, w01[t * 64 + h], a);
    }
    h0s[h] = fmaxf(a, 0.0f);
    __syncthreads();
    float a2 = b02[h];
#pragma unroll
    for (int k = 0; k < 64; k++) a2 = fmaf(h0s[k], w02[k * 64 + h], a2);
    ps[h] = fmaxf(a2, 0.0f) * w03[h];
    __syncthreads();
    if (h == 0) {
        float s = b03[0];
        for (int k = 0; k < 64; k++) s += ps[k];
        g_o0 = s;
    }
}

// ============================================================================
// Main kernel
// ============================================================================
constexpr int OFF_XHI  = 0;              // 128x64 bf16 hi tile, swizzled (16KB)
constexpr int OFF_XLO  = 16384;          // lo tile (16KB)
constexpr int OFF_W    = 32768;          // 2 buffers x 32768B (W1hi,W1lo,W2hi,W2lo)
constexpr int OFF_BIAS = 98304;          // 2 buffers x 832B
constexpr int SMEM_BYTES = 99968;

__device__ __forceinline__ void stage_i(char* smem, int i, int buf, int tid) {
    const unsigned char* src = g_wpack + (size_t)i * 32768;
    uint32_t dst = smem_u32(smem + OFF_W + buf * 32768);
#pragma unroll
    for (int j = 0; j < 16; j++) {
        int c = tid + j * 128;   // 2048 chunks of 16B
        asm volatile("cp.async.cg.shared.global [%0], [%1], 16;"
                     :: "r"(dst + c * 16), "l"(src + (size_t)c * 16));
    }
    if (tid < 52) {
        const float* bsrc = g_bpack + (size_t)i * 208;
        uint32_t bdst = smem_u32(smem + OFF_BIAS + buf * 832) + tid * 16;
        asm volatile("cp.async.cg.shared.global [%0], [%1], 16;"
                     :: "r"(bdst), "l"((const char*)bsrc + tid * 16));
    }
    asm volatile("cp.async.commit_group;" ::: "memory");
}

__global__ void __launch_bounds__(128, 2)
mlplist_main_kernel(const float* __restrict__ x, float* __restrict__ out, int B) {
    extern __shared__ char smem[];
    const int tid  = threadIdx.x;
    const int warp = tid >> 5, lane = tid & 31;
    const int tig  = lane & 3, grp = lane >> 2;
    const uint32_t sw = (uint32_t)grp << 4;      // XOR swizzle (row&7 == grp everywhere)
    const int rowBase = blockIdx.x * 128;
    const float o0 = g_o0;

    // ---- load & split X tile (thread = row) ----
    {
        const int row = rowBase + tid;
        if (row < B) {
            const float4* xr = (const float4*)(x + (size_t)row * DK);
#pragma unroll
            for (int c = 0; c < 8; c++) {
                float4 f0 = xr[2 * c], f1 = xr[2 * c + 1];
                uint4 hp, lp;
                split2(f0.x, f0.y, hp.x, lp.x);
                split2(f0.z, f0.w, hp.y, lp.y);
                split2(f1.x, f1.y, hp.z, lp.z);
                split2(f1.z, f1.w, hp.w, lp.w);
                uint32_t off = (uint32_t)(tid * 128) + (uint32_t)((c * 16) ^ ((tid & 7) << 4));
                *(uint4*)(smem + OFF_XHI + off) = hp;
                *(uint4*)(smem + OFF_XLO + off) = lp;
            }
        }
    }

    // prologue: stage weights for i=0
    stage_i(smem, 0, 0, tid);

    for (int i = 0; i < NI; i++) {
        const int buf = i & 1;
        __syncthreads();                       // prior reads of buf^1 done
        if (i + 1 < NI) {
            stage_i(smem, i + 1, buf ^ 1, tid);
            asm volatile("cp.async.wait_group 1;" ::: "memory");
        } else {
            asm volatile("cp.async.wait_group 0;" ::: "memory");
        }
        __syncthreads();

        const char*  Wb   = smem + OFF_W + buf * 32768;
        const float* bias = (const float*)(smem + OFF_BIAS + buf * 832);
        const float* b1v = bias, * b2v = bias + 64, * w3v = bias + 128;
        const float  b3v = bias[192];

        float acc[2][8][4];
#pragma unroll
        for (int m = 0; m < 2; m++)
#pragma unroll
            for (int j = 0; j < 8; j++)
#pragma unroll
                for (int r = 0; r < 4; r++) acc[m][j][r] = 0.0f;

        // ---- Layer 1: acc += Xsplit @ W1split^T (skip masked-zero K tiles) ----
        const int kt1 = (i >> 4) + 1;
        for (int kt = 0; kt < kt1; kt++) {
            uint32_t aH[2][4], aL[2][4];
            const uint32_t k0 = (uint32_t)(kt * 32 + tig * 4);
#pragma unroll
            for (int m = 0; m < 2; m++) {
                // FIX (R3): include warp's 32-row offset in the A-tile row
                const int r0 = warp * 32 + m * 16 + grp, r1 = r0 + 8;
                const uint32_t o00 = r0 * 128 + (k0 ^ sw);
                const uint32_t o10 = r1 * 128 + (k0 ^ sw);
                const uint32_t o01 = r0 * 128 + ((k0 + 16) ^ sw);
                const uint32_t o11 = r1 * 128 + ((k0 + 16) ^ sw);
                aH[m][0] = *(const uint32_t*)(smem + OFF_XHI + o00);
                aH[m][1] = *(const uint32_t*)(smem + OFF_XHI + o10);
                aH[m][2] = *(const uint32_t*)(smem + OFF_XHI + o01);
                aH[m][3] = *(const uint32_t*)(smem + OFF_XHI + o11);
                aL[m][0] = *(const uint32_t*)(smem + OFF_XLO + o00);
                aL[m][1] = *(const uint32_t*)(smem + OFF_XLO + o10);
                aL[m][2] = *(const uint32_t*)(smem + OFF_XLO + o01);
                aL[m][3] = *(const uint32_t*)(smem + OFF_XLO + o11);
            }
#pragma unroll
            for (int j = 0; j < 8; j++) {
                const int n = j * 8 + grp;
                const uint32_t ob0 = n * 128 + (k0 ^ sw);
                const uint32_t ob1 = n * 128 + ((k0 + 16) ^ sw);
                uint32_t bH[2], bL[2];
                bH[0] = *(const uint32_t*)(Wb + 0 * 8192 + ob0);
                bH[1] = *(const uint32_t*)(Wb + 0 * 8192 + ob1);
                bL[0] = *(const uint32_t*)(Wb + 1 * 8192 + ob0);
                bL[1] = *(const uint32_t*)(Wb + 1 * 8192 + ob1);
#pragma unroll
                for (int m = 0; m < 2; m++) {
                    mma16816(acc[m][j], aH[m], bH);
                    mma16816(acc[m][j], aH[m], bL);
                    mma16816(acc[m][j], aL[m], bH);
                }
            }
        }

        // ---- bias + relu + split -> layer-2 A fragments (registers only) ----
        uint32_t A2H[2][4][4], A2L[2][4][4];
#pragma unroll
        for (int m = 0; m < 2; m++)
#pragma unroll
            for (int k2 = 0; k2 < 4; k2++) {
                const int j0 = 2 * k2, j1 = 2 * k2 + 1;
                const int c0 = j0 * 8 + 2 * tig;
                const int c1 = j1 * 8 + 2 * tig;
                const float bb00 = b1v[c0], bb01 = b1v[c0 + 1];
                const float bb10 = b1v[c1], bb11 = b1v[c1 + 1];
                float v00 = fmaxf(acc[m][j0][0] + bb00, 0.f);
                float v01 = fmaxf(acc[m][j0][1] + bb01, 0.f);
                float v02 = fmaxf(acc[m][j0][2] + bb00, 0.f);
                float v03 = fmaxf(acc[m][j0][3] + bb01, 0.f);
                float v10 = fmaxf(acc[m][j1][0] + bb10, 0.f);
                float v11 = fmaxf(acc[m][j1][1] + bb11, 0.f);
                float v12 = fmaxf(acc[m][j1][2] + bb10, 0.f);
                float v13 = fmaxf(acc[m][j1][3] + bb11, 0.f);
                split2(v00, v01, A2H[m][k2][0], A2L[m][k2][0]);
                split2(v02, v03, A2H[m][k2][1], A2L[m][k2][1]);
                split2(v10, v11, A2H[m][k2][2], A2L[m][k2][2]);
                split2(v12, v13, A2H[m][k2][3], A2L[m][k2][3]);
            }

        // ---- Layer 2 ----
#pragma unroll
        for (int m = 0; m < 2; m++)
#pragma unroll
            for (int j = 0; j < 8; j++)
#pragma unroll
                for (int r = 0; r < 4; r++) acc[m][j][r] = 0.0f;

#pragma unroll
        for (int k2 = 0; k2 < 4; k2++) {
            const uint32_t k0 = (uint32_t)(k2 * 32 + tig * 4);
#pragma unroll
            for (int j = 0; j < 8; j++) {
                const int n = j * 8 + grp;
                const uint32_t ob0 = n * 128 + (k0 ^ sw);
                const uint32_t ob1 = n * 128 + ((k0 + 16) ^ sw);
                uint32_t bH[2], bL[2];
                bH[0] = *(const uint32_t*)(Wb + 2 * 8192 + ob0);
                bH[1] = *(const uint32_t*)(Wb + 2 * 8192 + ob1);
                bL[0] = *(const uint32_t*)(Wb + 3 * 8192 + ob0);
                bL[1] = *(const uint32_t*)(Wb + 3 * 8192 + ob1);
#pragma unroll
                for (int m = 0; m < 2; m++) {
                    mma16816(acc[m][j], A2H[m][k2], bH);
                    mma16816(acc[m][j], A2H[m][k2], bL);
                    mma16816(acc[m][j], A2L[m][k2], bH);
                }
            }
        }

        // ---- Layer 3: bias + relu + dot(w3) + quad reduce + store ----
#pragma unroll
        for (int m = 0; m < 2; m++) {
            float p0 = 0.f, p1 = 0.f;
#pragma unroll
            for (int j = 0; j < 8; j++) {
                const int c = 8 * j + 2 * tig;
                const float w0 = w3v[c], w1 = w3v[c + 1];
                const float bb0 = b2v[c], bb1 = b2v[c + 1];
                p0 += fmaxf(acc[m][j][0] + bb0, 0.f) * w0
                    + fmaxf(acc[m][j][1] + bb1, 0.f) * w1;
                p1 += fmaxf(acc[m][j][2] + bb0, 0.f) * w0
                    + fmaxf(acc[m][j][3] + bb1, 0.f) * w1;
            }
            p0 += __shfl_xor_sync(0xFFFFFFFFu, p0, 1);
            p0 += __shfl_xor_sync(0xFFFFFFFFu, p0, 2);
            p1 += __shfl_xor_sync(0xFFFFFFFFu, p1, 1);
            p1 += __shfl_xor_sync(0xFFFFFFFFu, p1, 2);
            if (tig == 0) {
                const int row = rowBase + warp * 32 + m * 16 + grp;
                if (row < B)     out[(size_t)row * 64 + (i + 1)]       = p0 + b3v;
                if (row + 8 < B) out[(size_t)(row + 8) * 64 + (i + 1)] = p1 + b3v;
            }
        }
    }

    // dim-0 column (batch-constant)
    if (rowBase + tid < B) out[(size_t)(rowBase + tid) * 64] = o0;
}

// ============================================================================
// Launch
// ============================================================================
extern "C" void kernel_launch(void* const* d_in, const int* in_sizes, int n_in,
                              void* d_out, int out_size) {
    const float* x   = (const float*)d_in[0];
    const float* W1  = (const float*)d_in[1];
    const float* b1  = (const float*)d_in[2];
    const float* W2  = (const float*)d_in[3];
    const float* b2  = (const float*)d_in[4];
    const float* W3  = (const float*)d_in[5];
    const float* b3  = (const float*)d_in[6];
    const float* w01 = (const float*)d_in[7];
    const float* b01 = (const float*)d_in[8];
    const float* w02 = (const float*)d_in[9];
    const float* b02 = (const float*)d_in[10];
    const float* w03 = (const float*)d_in[11];
    const float* b03 = (const float*)d_in[12];
    float* out = (float*)d_out;

    const int B = in_sizes[0] / DK;

    prep_weights_kernel<<<(NI * DK * HN + 255) / 256, 256>>>(W1, W2);
    prep_bias_kernel<<<(NI * 208 + 255) / 256, 256>>>(b1, b2, W3, b3);
    prep_dim0_kernel<<<1, 64>>>(w01, b01, w02, b02, w03, b03);

    static bool attr_set = false;
    if (!attr_set) {
        cudaFuncSetAttribute(mlplist_main_kernel,
                             cudaFuncAttributeMaxDynamicSharedMemorySize, SMEM_BYTES);
        attr_set = true;
    }
    const int grid = (B + 127) / 128;
    mlplist_main_kernel<<<grid, 128, SMEM_BYTES>>>(x, out, B);
}

// round 4
// speedup vs baseline: 1.0076x; 1.0076x over previous
#include <cuda_runtime.h>
#include <cuda_bf16.h>
#include <cstdint>

// ============================================================================
// MLPList: B=32768 rows, 63 stacked MLPs (64->64->64->1), causal input mask.
// Warp-level mma.sync bf16 hi/lo split; weights pre-masked/transposed/split/
// swizzled in device scratch; cp.async double-buffered staging; register-only
// layer1->layer2 handoff. R4: product-major MMA ordering (acc reuse distance
// 16) to fill the tensor pipe at low occupancy.
// ============================================================================
#define NI 63
#define DK 64
#define HN 64

__device__ __align__(16) unsigned char g_wpack[NI * 32768];
__device__ __align__(16) float g_bpack[NI * 208];   // b1[64], b2[64], w3[64], b3, pad
__device__ float g_o0;

// ---------------------------------------------------------------------------
__device__ __forceinline__ uint32_t smem_u32(const void* p) {
    uint32_t a;
    asm("{ .reg .u64 t; cvta.to.shared.u64 t, %1; cvt.u32.u64 %0, t; }"
        : "=r"(a) : "l"(p));
    return a;
}

__device__ __forceinline__ void split2(float a, float b, uint32_t& hi, uint32_t& lo) {
    __nv_bfloat16 ha = __float2bfloat16(a), hb = __float2bfloat16(b);
    float ra = a - __bfloat162float(ha);
    float rb = b - __bfloat162float(hb);
    __nv_bfloat16 la = __float2bfloat16(ra), lb = __float2bfloat16(rb);
    hi = ((uint32_t)__bfloat16_as_ushort(hb) << 16) | (uint32_t)__bfloat16_as_ushort(ha);
    lo = ((uint32_t)__bfloat16_as_ushort(lb) << 16) | (uint32_t)__bfloat16_as_ushort(la);
}

__device__ __forceinline__ void mma16816(float* d, const uint32_t* a, const uint32_t* b) {
    asm volatile(
        "mma.sync.aligned.m16n8k16.row.col.f32.bf16.bf16.f32 "
        "{%0,%1,%2,%3}, {%4,%5,%6,%7}, {%8,%9}, {%0,%1,%2,%3};"
        : "+f"(d[0]), "+f"(d[1]), "+f"(d[2]), "+f"(d[3])
        : "r"(a[0]), "r"(a[1]), "r"(a[2]), "r"(a[3]), "r"(b[0]), "r"(b[1]));
}

// ============================================================================
// Prep kernels
// ============================================================================
__global__ void prep_weights_kernel(const float* __restrict__ W1,
                                    const float* __restrict__ W2) {
    int idx = blockIdx.x * blockDim.x + threadIdx.x;
    if (idx >= NI * DK * HN) return;
    int i = idx >> 12;
    int n = (idx >> 6) & 63;
    int k = idx & 63;
    uint32_t off = (uint32_t)(n * 128) + (uint32_t)((k * 2) ^ ((n & 7) << 4));
    unsigned char* base = g_wpack + (size_t)i * 32768;

    float v1 = (k <= i) ? W1[((size_t)i * DK + k) * HN + n] : 0.0f;
    __nv_bfloat16 h1 = __float2bfloat16(v1);
    __nv_bfloat16 l1 = __float2bfloat16(v1 - __bfloat162float(h1));
    *(__nv_bfloat16*)(base + 0 * 8192 + off) = h1;
    *(__nv_bfloat16*)(base + 1 * 8192 + off) = l1;

    float v2 = W2[((size_t)i * HN + k) * HN + n];
    __nv_bfloat16 h2 = __float2bfloat16(v2);
    __nv_bfloat16 l2 = __float2bfloat16(v2 - __bfloat162float(h2));
    *(__nv_bfloat16*)(base + 2 * 8192 + off) = h2;
    *(__nv_bfloat16*)(base + 3 * 8192 + off) = l2;
}

__global__ void prep_bias_kernel(const float* __restrict__ b1, const float* __restrict__ b2,
                                 const float* __restrict__ W3, const float* __restrict__ b3) {
    int idx = blockIdx.x * blockDim.x + threadIdx.x;
    if (idx >= NI * 208) return;
    int i = idx / 208, t = idx % 208;
    float v = 0.0f;
    if (t < 64)       v = b1[i * 64 + t];
    else if (t < 128) v = b2[i * 64 + (t - 64)];
    else if (t < 192) v = W3[i * 64 + (t - 128)];
    else if (t == 192) v = b3[i];
    g_bpack[i * 208 + t] = v;
}

__global__ void prep_dim0_kernel(const float* __restrict__ w01, const float* __restrict__ b01,
                                 const float* __restrict__ w02, const float* __restrict__ b02,
                                 const float* __restrict__ w03, const float* __restrict__ b03) {
    __shared__ float h0s[64];
    __shared__ float ps[64];
    int h = threadIdx.x;
    float a = b01[h];
#pragma unroll
    for (int t = 0; t < 10; t++) {
        float v = 0.1f * (-5.0f + (float)t * (10.0f / 9.0f));
        a = fmaf(v, w01[t * 64 + h], a);
    }
    h0s[h] = fmaxf(a, 0.0f);
    __syncthreads();
    float a2 = b02[h];
#pragma unroll
    for (int k = 0; k < 64; k++) a2 = fmaf(h0s[k], w02[k * 64 + h], a2);
    ps[h] = fmaxf(a2, 0.0f) * w03[h];
    __syncthreads();
    if (h == 0) {
        float s = b03[0];
        for (int k = 0; k < 64; k++) s += ps[k];
        g_o0 = s;
    }
}

// ============================================================================
// Main kernel
// ============================================================================
constexpr int OFF_XHI  = 0;
constexpr int OFF_XLO  = 16384;
constexpr int OFF_W    = 32768;          // 2 x 32768B (W1hi,W1lo,W2hi,W2lo)
constexpr int OFF_BIAS = 98304;          // 2 x 832B
constexpr int SMEM_BYTES = 99968;

__device__ __forceinline__ void stage_i(char* smem, int i, int buf, int tid) {
    const unsigned char* src = g_wpack + (size_t)i * 32768;
    uint32_t dst = smem_u32(smem + OFF_W + buf * 32768);
#pragma unroll
    for (int j = 0; j < 16; j++) {
        int c = tid + j * 128;
        asm volatile("cp.async.cg.shared.global [%0], [%1], 16;"
                     :: "r"(dst + c * 16), "l"(src + (size_t)c * 16));
    }
    if (tid < 52) {
        const float* bsrc = g_bpack + (size_t)i * 208;
        uint32_t bdst = smem_u32(smem + OFF_BIAS + buf * 832) + tid * 16;
        asm volatile("cp.async.cg.shared.global [%0], [%1], 16;"
                     :: "r"(bdst), "l"((const char*)bsrc + tid * 16));
    }
    asm volatile("cp.async.commit_group;" ::: "memory");
}

__global__ void __launch_bounds__(128, 2)
mlplist_main_kernel(const float* __restrict__ x, float* __restrict__ out, int B) {
    extern __shared__ char smem[];
    const int tid  = threadIdx.x;
    const int warp = tid >> 5, lane = tid & 31;
    const int tig  = lane & 3, grp = lane >> 2;
    const uint32_t sw = (uint32_t)grp << 4;
    const int rowBase = blockIdx.x * 128;
    const float o0 = g_o0;

    // ---- load & split X tile (thread = row) ----
    {
        const int row = rowBase + tid;
        if (row < B) {
            const float4* xr = (const float4*)(x + (size_t)row * DK);
#pragma unroll
            for (int c = 0; c < 8; c++) {
                float4 f0 = xr[2 * c], f1 = xr[2 * c + 1];
                uint4 hp, lp;
                split2(f0.x, f0.y, hp.x, lp.x);
                split2(f0.z, f0.w, hp.y, lp.y);
                split2(f1.x, f1.y, hp.z, lp.z);
                split2(f1.z, f1.w, hp.w, lp.w);
                uint32_t off = (uint32_t)(tid * 128) + (uint32_t)((c * 16) ^ ((tid & 7) << 4));
                *(uint4*)(smem + OFF_XHI + off) = hp;
                *(uint4*)(smem + OFF_XLO + off) = lp;
            }
        }
    }

    stage_i(smem, 0, 0, tid);

    for (int i = 0; i < NI; i++) {
        const int buf = i & 1;
        __syncthreads();
        if (i + 1 < NI) {
            stage_i(smem, i + 1, buf ^ 1, tid);
            asm volatile("cp.async.wait_group 1;" ::: "memory");
        } else {
            asm volatile("cp.async.wait_group 0;" ::: "memory");
        }
        __syncthreads();

        const char*  Wb   = smem + OFF_W + buf * 32768;
        const float* bias = (const float*)(smem + OFF_BIAS + buf * 832);
        const float* b1v = bias, * b2v = bias + 64, * w3v = bias + 128;
        const float  b3v = bias[192];

        float acc[2][8][4];
#pragma unroll
        for (int m = 0; m < 2; m++)
#pragma unroll
            for (int j = 0; j < 8; j++)
#pragma unroll
                for (int r = 0; r < 4; r++) acc[m][j][r] = 0.0f;

        // ---- Layer 1 (product-major MMA order, acc reuse distance = 16) ----
        const int kt1 = (i >> 4) + 1;
        for (int kt = 0; kt < kt1; kt++) {
            const uint32_t k0 = (uint32_t)(kt * 32 + tig * 4);
            uint32_t aH[2][4], aL[2][4];
#pragma unroll
            for (int m = 0; m < 2; m++) {
                const int r0 = warp * 32 + m * 16 + grp, r1 = r0 + 8;
                const uint32_t o00 = r0 * 128 + (k0 ^ sw);
                const uint32_t o10 = r1 * 128 + (k0 ^ sw);
                const uint32_t o01 = r0 * 128 + ((k0 + 16) ^ sw);
                const uint32_t o11 = r1 * 128 + ((k0 + 16) ^ sw);
                aH[m][0] = *(const uint32_t*)(smem + OFF_XHI + o00);
                aH[m][1] = *(const uint32_t*)(smem + OFF_XHI + o10);
                aH[m][2] = *(const uint32_t*)(smem + OFF_XHI + o01);
                aH[m][3] = *(const uint32_t*)(smem + OFF_XHI + o11);
                aL[m][0] = *(const uint32_t*)(smem + OFF_XLO + o00);
                aL[m][1] = *(const uint32_t*)(smem + OFF_XLO + o10);
                aL[m][2] = *(const uint32_t*)(smem + OFF_XLO + o01);
                aL[m][3] = *(const uint32_t*)(smem + OFF_XLO + o11);
            }
            uint32_t bH[8][2], bL[8][2];
#pragma unroll
            for (int j = 0; j < 8; j++) {
                const int n = j * 8 + grp;
                const uint32_t ob0 = n * 128 + (k0 ^ sw);
                const uint32_t ob1 = n * 128 + ((k0 + 16) ^ sw);
                bH[j][0] = *(const uint32_t*)(Wb + 0 * 8192 + ob0);
                bH[j][1] = *(const uint32_t*)(Wb + 0 * 8192 + ob1);
                bL[j][0] = *(const uint32_t*)(Wb + 1 * 8192 + ob0);
                bL[j][1] = *(const uint32_t*)(Wb + 1 * 8192 + ob1);
            }
#pragma unroll
            for (int j = 0; j < 8; j++) {
                mma16816(acc[0][j], aH[0], bH[j]);
                mma16816(acc[1][j], aH[1], bH[j]);
            }
#pragma unroll
            for (int j = 0; j < 8; j++) {
                mma16816(acc[0][j], aH[0], bL[j]);
                mma16816(acc[1][j], aH[1], bL[j]);
            }
#pragma unroll
            for (int j = 0; j < 8; j++) {
                mma16816(acc[0][j], aL[0], bH[j]);
                mma16816(acc[1][j], aL[1], bH[j]);
            }
        }

        // ---- bias + relu + split -> layer-2 A fragments (registers only) ----
        uint32_t A2H[2][4][4], A2L[2][4][4];
#pragma unroll
        for (int m = 0; m < 2; m++)
#pragma unroll
            for (int k2 = 0; k2 < 4; k2++) {
                const int j0 = 2 * k2, j1 = 2 * k2 + 1;
                const int c0 = j0 * 8 + 2 * tig;
                const int c1 = j1 * 8 + 2 * tig;
                const float bb00 = b1v[c0], bb01 = b1v[c0 + 1];
                const float bb10 = b1v[c1], bb11 = b1v[c1 + 1];
                float v00 = fmaxf(acc[m][j0][0] + bb00, 0.f);
                float v01 = fmaxf(acc[m][j0][1] + bb01, 0.f);
                float v02 = fmaxf(acc[m][j0][2] + bb00, 0.f);
                float v03 = fmaxf(acc[m][j0][3] + bb01, 0.f);
                float v10 = fmaxf(acc[m][j1][0] + bb10, 0.f);
                float v11 = fmaxf(acc[m][j1][1] + bb11, 0.f);
                float v12 = fmaxf(acc[m][j1][2] + bb10, 0.f);
                float v13 = fmaxf(acc[m][j1][3] + bb11, 0.f);
                split2(v00, v01, A2H[m][k2][0], A2L[m][k2][0]);
                split2(v02, v03, A2H[m][k2][1], A2L[m][k2][1]);
                split2(v10, v11, A2H[m][k2][2], A2L[m][k2][2]);
                split2(v12, v13, A2H[m][k2][3], A2L[m][k2][3]);
            }

        // ---- Layer 2 (product-major within each k2) ----
#pragma unroll
        for (int m = 0; m < 2; m++)
#pragma unroll
            for (int j = 0; j < 8; j++)
#pragma unroll
                for (int r = 0; r < 4; r++) acc[m][j][r] = 0.0f;

#pragma unroll
        for (int k2 = 0; k2 < 4; k2++) {
            const uint32_t k0 = (uint32_t)(k2 * 32 + tig * 4);
            uint32_t bH[8][2], bL[8][2];
#pragma unroll
            for (int j = 0; j < 8; j++) {
                const int n = j * 8 + grp;
                const uint32_t ob0 = n * 128 + (k0 ^ sw);
                const uint32_t ob1 = n * 128 + ((k0 + 16) ^ sw);
                bH[j][0] = *(const uint32_t*)(Wb + 2 * 8192 + ob0);
                bH[j][1] = *(const uint32_t*)(Wb + 2 * 8192 + ob1);
                bL[j][0] = *(const uint32_t*)(Wb + 3 * 8192 + ob0);
                bL[j][1] = *(const uint32_t*)(Wb + 3 * 8192 + ob1);
            }
#pragma unroll
            for (int j = 0; j < 8; j++) {
                mma16816(acc[0][j], A2H[0][k2], bH[j]);
                mma16816(acc[1][j], A2H[1][k2], bH[j]);
            }
#pragma unroll
            for (int j = 0; j < 8; j++) {
                mma16816(acc[0][j], A2H[0][k2], bL[j]);
                mma16816(acc[1][j], A2H[1][k2], bL[j]);
            }
#pragma unroll
            for (int j = 0; j < 8; j++) {
                mma16816(acc[0][j], A2L[0][k2], bH[j]);
                mma16816(acc[1][j], A2L[1][k2], bH[j]);
            }
        }

        // ---- Layer 3: bias + relu + dot(w3) + quad reduce + store ----
#pragma unroll
        for (int m = 0; m < 2; m++) {
            float p0 = 0.f, p1 = 0.f;
#pragma unroll
            for (int j = 0; j < 8; j++) {
                const int c = 8 * j + 2 * tig;
                const float w0 = w3v[c], w1 = w3v[c + 1];
                const float bb0 = b2v[c], bb1 = b2v[c + 1];
                p0 += fmaxf(acc[m][j][0] + bb0, 0.f) * w0
                    + fmaxf(acc[m][j][1] + bb1, 0.f) * w1;
                p1 += fmaxf(acc[m][j][2] + bb0, 0.f) * w0
                    + fmaxf(acc[m][j][3] + bb1, 0.f) * w1;
            }
            p0 += __shfl_xor_sync(0xFFFFFFFFu, p0, 1);
            p0 += __shfl_xor_sync(0xFFFFFFFFu, p0, 2);
            p1 += __shfl_xor_sync(0xFFFFFFFFu, p1, 1);
            p1 += __shfl_xor_sync(0xFFFFFFFFu, p1, 2);
            if (tig == 0) {
                const int row = rowBase + warp * 32 + m * 16 + grp;
                if (row < B)     out[(size_t)row * 64 + (i + 1)]       = p0 + b3v;
                if (row + 8 < B) out[(size_t)(row + 8) * 64 + (i + 1)] = p1 + b3v;
            }
        }
    }

    if (rowBase + tid < B) out[(size_t)(rowBase + tid) * 64] = o0;
}

// ============================================================================
// Launch
// ============================================================================
extern "C" void kernel_launch(void* const* d_in, const int* in_sizes, int n_in,
                              void* d_out, int out_size) {
    const float* x   = (const float*)d_in[0];
    const float* W1  = (const float*)d_in[1];
    const float* b1  = (const float*)d_in[2];
    const float* W2  = (const float*)d_in[3];
    const float* b2  = (const float*)d_in[4];
    const float* W3  = (const float*)d_in[5];
    const float* b3  = (const float*)d_in[6];
    const float* w01 = (const float*)d_in[7];
    const float* b01 = (const float*)d_in[8];
    const float* w02 = (const float*)d_in[9];
    const float* b02 = (const float*)d_in[10];
    const float* w03 = (const float*)d_in[11];
    const float* b03 = (const float*)d_in[12];
    float* out = (float*)d_out;

    const int B = in_sizes[0] / DK;

    prep_weights_kernel<<<(NI * DK * HN + 255) / 256, 256>>>(W1, W2);
    prep_bias_kernel<<<(NI * 208 + 255) / 256, 256>>>(b1, b2, W3, b3);
    prep_dim0_kernel<<<1, 64>>>(w01, b01, w02, b02, w03, b03);

    static bool attr_set = false;
    if (!attr_set) {
        cudaFuncSetAttribute(mlplist_main_kernel,
                             cudaFuncAttributeMaxDynamicSharedMemorySize, SMEM_BYTES);
        attr_set = true;
    }
    const int grid = (B + 127) / 128;
    mlplist_main_kernel<<<grid, 128, SMEM_BYTES>>>(x, out, B);
}